// round 11
// baseline (speedup 1.0000x reference)
#include <cuda_runtime.h>

#define FULLM 0xffffffffu

typedef unsigned long long ull;

constexpr int NQ  = 10;
constexpr int DIN = 256;
constexpr int WPB = 4;      // warps (samples) per block
constexpr int TS  = 34;     // transpose row stride (ull): conflict-free both directions

__host__ __device__ constexpr int par(unsigned v) {
    int p = 0;
    while (v) { p ^= (v & 1); v >>= 1; }
    return p;
}

// inverse of the Jbits map: k -> j with Jbits(j) = k
// Jbits: k0=e0, k1=e1, k2=e0^e2, k3=e1^e3, k4=e0^e2^e4
// =>     e0=k0, e1=k1, e2=k0^k2, e3=k1^k3, e4=k2^k4
__host__ __device__ constexpr int jinv(int k) {
    const int e0 = k & 1;
    const int e1 = (k >> 1) & 1;
    const int e2 = e0 ^ ((k >> 2) & 1);
    const int e3 = e1 ^ ((k >> 3) & 1);
    const int e4 = ((k >> 2) & 1) ^ ((k >> 4) & 1);   // k2 ^ k4
    return e0 | (e1 << 1) | (e2 << 2) | (e3 << 3) | (e4 << 4);
}

// ---- packed f32x2 helpers (sm_103a FFMA2 path) -----------------------------
__device__ __forceinline__ ull pk2(float lo, float hi) {
    ull r; asm("mov.b64 %0, {%1, %2};" : "=l"(r) : "f"(lo), "f"(hi)); return r;
}
__device__ __forceinline__ void upk2(float& lo, float& hi, ull v) {
    asm("mov.b64 {%0, %1}, %2;" : "=f"(lo), "=f"(hi) : "l"(v));
}
__device__ __forceinline__ ull swap2(ull v) {
    float lo, hi; upk2(lo, hi, v); return pk2(hi, lo);
}
__device__ __forceinline__ ull fma2(ull a, ull b, ull c) {
    ull d; asm("fma.rn.f32x2 %0, %1, %2, %3;" : "=l"(d) : "l"(a), "l"(b), "l"(c)); return d;
}
__device__ __forceinline__ ull mul2(ull a, ull b) {
    ull d; asm("mul.rn.f32x2 %0, %1, %2;" : "=l"(d) : "l"(a), "l"(b)); return d;
}
__device__ __forceinline__ ull add2(ull a, ull b) {
    ull d; asm("add.rn.f32x2 %0, %1, %2;" : "=l"(d) : "l"(a), "l"(b)); return d;
}

// Tangent-form RY rotation pairing slots (j, j^MASK); cos factored out globally.
//   st[j] = a0 + rj*a1 ; st[j2] = a1 - rj*a0 ; rj = (lp ^ par(j&PARJ)) ? +r : -r
template<int MASK, unsigned PARJ>
__device__ __forceinline__ void rot_tan(ull (&st)[32], float r, int lp)
{
    const float rr = lp ? r : -r;
    const ull rp0 = pk2(rr, rr);
    const ull rn0 = pk2(-rr, -rr);
    constexpr int LOW = MASK & (-MASK);
#pragma unroll
    for (int j = 0; j < 32; ++j) {
        if ((j & LOW) == 0) {
            const int j2 = j ^ MASK;
            const ull rp = par((unsigned)j & PARJ) ? rn0 : rp0;
            const ull rn = par((unsigned)j & PARJ) ? rp0 : rn0;
            ull a0 = st[j], a1 = st[j2];
            st[j]  = fma2(rp, a1, a0);
            st[j2] = fma2(rn, a0, a1);
        }
    }
}

__global__ void __launch_bounds__(WPB * 32, 5)
vqc_kernel(const float* __restrict__ x, const float* __restrict__ W,
           const float* __restrict__ b, const float* __restrict__ theta,
           float* __restrict__ out, int batch)
{
    // Wp[p][d] = packed (W[d][2p], W[d][2p+1])
    __shared__ __align__(16) ull Wp[5][DIN];
    __shared__ __align__(16) ull tb[WPB][32 * TS];   // padded transpose buffer
    __shared__ float bsh[NQ];
    __shared__ float thh[NQ];                // 0.5*theta[0][q][0]
    __shared__ float cz1[NQ], sz1[NQ];       // layer-1 RZ HALF-angle cos/sin
    __shared__ float czf[NQ], szf[NQ];       // layer-1 RZ FULL-angle cos/sin (for v ratio)
    __shared__ float ty2[NQ];                // tan of layer-2 RY half-angle
    __shared__ float Fsq;                    // (prod_q cos(half))^2

    const int tid = threadIdx.x;

    {
        const ull* Wsrc = reinterpret_cast<const ull*>(W);
        for (int m = tid; m < 5 * DIN; m += blockDim.x) {
            int d = m / 5, p = m - d * 5;
            Wp[p][d] = Wsrc[m];
        }
    }
    if (tid < NQ) {
        bsh[tid] = b[tid];
        thh[tid] = 0.5f * theta[tid * 2 + 0];
        float z1 = theta[tid * 2 + 1];
        float hz1 = 0.5f * z1;
        cz1[tid] = cosf(hz1); sz1[tid] = sinf(hz1);
        czf[tid] = cosf(z1);  szf[tid] = sinf(z1);
        float hy2 = 0.5f * theta[(NQ + tid) * 2 + 0];
        ty2[tid] = tanf(hy2);
    }
    if (tid == 32) {
        float F = 1.f;
#pragma unroll
        for (int q = 0; q < NQ; ++q)
            F *= cosf(0.5f * theta[(NQ + q) * 2 + 0]);
        Fsq = F * F;
    }
    __syncthreads();

    const int warp = blockIdx.x * WPB + (tid >> 5);
    if (warp >= batch) return;
    const int lane = tid & 31;
    ull* buf = tb[tid >> 5];

    // ---------------- Dense encoder (packed: 2 qubits per accumulator) ------
    float ang[NQ];
    {
        const float4* xr = reinterpret_cast<const float4*>(x + (size_t)warp * DIN);
        float4 xv0 = xr[lane];
        float4 xv1 = xr[lane + 32];
        ull xp[8];
        xp[0] = pk2(xv0.x, xv0.x); xp[1] = pk2(xv0.y, xv0.y);
        xp[2] = pk2(xv0.z, xv0.z); xp[3] = pk2(xv0.w, xv0.w);
        xp[4] = pk2(xv1.x, xv1.x); xp[5] = pk2(xv1.y, xv1.y);
        xp[6] = pk2(xv1.z, xv1.z); xp[7] = pk2(xv1.w, xv1.w);
#pragma unroll
        for (int p = 0; p < 5; ++p) {
            const ulonglong2* wr = reinterpret_cast<const ulonglong2*>(&Wp[p][0]);
            ulonglong2 wa = wr[2 * lane];
            ulonglong2 wb = wr[2 * lane + 1];
            ulonglong2 wc = wr[2 * lane + 64];
            ulonglong2 wd = wr[2 * lane + 65];
            ull acc2 = mul2(xp[0], wa.x);
            acc2 = fma2(xp[1], wa.y, acc2);
            acc2 = fma2(xp[2], wb.x, acc2);
            acc2 = fma2(xp[3], wb.y, acc2);
            acc2 = fma2(xp[4], wc.x, acc2);
            acc2 = fma2(xp[5], wc.y, acc2);
            acc2 = fma2(xp[6], wd.x, acc2);
            acc2 = fma2(xp[7], wd.y, acc2);
#pragma unroll
            for (int o = 16; o; o >>= 1)
                acc2 = add2(acc2, __shfl_xor_sync(FULLM, acc2, o));
            float a0, a1; upk2(a0, a1, acc2);
            ang[2 * p]     = a0 + bsh[2 * p];
            ang[2 * p + 1] = a1 + bsh[2 * p + 1];
        }
    }

    // ---------------- Initial product state (enc RY + L1 RY + L1 RZ) --------
    // Layout: reg bits 0..4 = phys 0..4, lane bits 0..4 = phys 5..9.
    float lfr = 1.f, lfi = 0.f;
#pragma unroll
    for (int qb = 0; qb < 5; ++qb) {
        const int q = 5 + qb;
        float h = 0.5f * ang[q] + thh[q];
        float sn, c;
        __sincosf(h, &sn, &c);
        float cz = cz1[q], sz = sz1[q];
        int bit = (lane >> qb) & 1;
        float amp = bit ? sn : c;
        float ph  = bit ? sz : -sz;
        float vr2 = amp * cz;
        float vi2 = amp * ph;
        float nr = lfr * vr2 - lfi * vi2;
        float ni = lfr * vi2 + lfi * vr2;
        lfr = nr; lfi = ni;
    }
    // Ratio-form doubling, fully packed:
    //   st[0] = P = lf * prod_q u0_q ;  new-half = old * v_q
    //   z*v = fma2(swap(z), (-vi,+vi), mul2(z, (vr,vr)))
    float Pr = lfr, Pi = lfi;
    ull vdup[5], vneg[5];
#pragma unroll
    for (int q = 0; q < 5; ++q) {
        float h = 0.5f * ang[q] + thh[q];
        float sn, c;
        __sincosf(h, &sn, &c);
        float t = __fdividef(sn, c);
        float vrq = t * czf[q];
        float viq = t * szf[q];
        vdup[q] = pk2(vrq, vrq);
        vneg[q] = pk2(-viq, viq);
        float u0r = c * cz1[q], u0i = -c * sz1[q];
        float nr = Pr * u0r - Pi * u0i;
        float ni = Pr * u0i + Pi * u0r;
        Pr = nr; Pi = ni;
    }
    ull st[32];
    st[0] = pk2(Pr, Pi);
#pragma unroll
    for (int q = 0; q < 5; ++q) {
        const int n = 1 << q;
#pragma unroll
        for (int j = 0; j < n; ++j)
            st[j + n] = fma2(swap2(st[j]), vneg[q], mul2(st[j], vdup[q]));
    }

    // ---------------- CNOT chain #1 = relabeling. Rotations (tangent form) --
    rot_tan<0x03, 0x01>(st, ty2[0], 0);
    rot_tan<0x06, 0x03>(st, ty2[1], 0);
    rot_tan<0x0C, 0x07>(st, ty2[2], 0);
    rot_tan<0x18, 0x0F>(st, ty2[3], 0);

    // ---------------- Transpose reg<->lane bits with q4 FUSED ----------------
    // Element identity (low, high) = (pre reg j, pre lane). Address low*TS+high:
    //   writes: buf[j*TS + lane] (32 STS.64, banks 4j+2lane: conflict-free)
    //   reads : slot j needs (low=lane, high=j) -> buf[lane*TS + j], contiguous
    //           -> 16 LDS.128; partner (low=lane^16, high=j^1) is the OTHER
    //           half of the pair at row lane^16 -> free .x/.y selection.
    // b(slot) = par(lane); st_new = main + (b ? +r4 : -r4) * partner.
    {
#pragma unroll
        for (int j = 0; j < 32; ++j) buf[j * TS + lane] = st[j];
        __syncwarp();
        const float rb = (__popc(lane) & 1) ? ty2[4] : -ty2[4];
        const ull rbp = pk2(rb, rb);
        const int lx = lane ^ 16;
#pragma unroll
        for (int j = 0; j < 32; j += 2) {
            ulonglong2 mp = *reinterpret_cast<const ulonglong2*>(&buf[lane * TS + j]);
            ulonglong2 pp = *reinterpret_cast<const ulonglong2*>(&buf[lx * TS + j]);
            st[j]     = fma2(rbp, pp.y, mp.x);
            st[j + 1] = fma2(rbp, pp.x, mp.y);
        }
    }

    // q = 5..9 : reg-only. b = par(lane&31) ^ par(j & ((1<<(q-4))-1))
    {
        const int lp = __popc(lane & 0x1F) & 1;
        rot_tan<0x03, 0x01>(st, ty2[5], lp);
        rot_tan<0x06, 0x03>(st, ty2[6], lp);
        rot_tan<0x0C, 0x07>(st, ty2[7], lp);
        rot_tan<0x18, 0x0F>(st, ty2[8], lp);
        rot_tan<0x10, 0x1F>(st, ty2[9], lp);
    }

    // ---------------- CNOT chain #2 = relabeling + measurement ---------------
    // acc = (1-0.2*Llow)*S - 0.2*T, T = (pA ? 3S-E : E) + (pB ? 2S-O : O),
    // E = S0+S2+S4, O = S1+S3, Sm = sum_{k: bit m set} leaf(k), leaf(k)=|st[jinv(k)]|^2
    const int p0 = lane & 1;
    const int p1 = (lane >> 1) & 1;
    const int p2 = __popc(lane & 0x05) & 1;
    const int pA = __popc(lane & 0x0A) & 1;
    const int pB = __popc(lane & 0x15) & 1;
    const int Llow = p0 + p1 + p2 + pA + pB;

    ull pairv[16];
    ull odda[4] = {0, 0, 0, 0};
#pragma unroll
    for (int i = 0; i < 16; ++i) {
        const int ke = 2 * i, ko = 2 * i + 1;
        ull le = mul2(st[jinv(ke)], st[jinv(ke)]);
        ull lo = mul2(st[jinv(ko)], st[jinv(ko)]);
        pairv[i] = add2(le, lo);
        odda[i & 3] = add2(odda[i & 3], lo);
    }
    ull S0p = add2(add2(odda[0], odda[1]), add2(odda[2], odda[3]));

    ull t8[8];
#pragma unroll
    for (int m = 0; m < 8; ++m) t8[m] = add2(pairv[2 * m], pairv[2 * m + 1]);
    ull S1p = add2(add2(add2(pairv[1], pairv[3]), add2(pairv[5], pairv[7])),
                   add2(add2(pairv[9], pairv[11]), add2(pairv[13], pairv[15])));
    ull t4[4];
#pragma unroll
    for (int m = 0; m < 4; ++m) t4[m] = add2(t8[2 * m], t8[2 * m + 1]);
    ull S2p = add2(add2(t8[1], t8[3]), add2(t8[5], t8[7]));
    ull t2a = add2(t4[0], t4[1]);
    ull t2b = add2(t4[2], t4[3]);
    ull S3p = add2(t4[1], t4[3]);
    ull S4p = t2b;
    ull Sp  = add2(t2a, t2b);

    float lo, hi;
    upk2(lo, hi, Sp);  const float S  = lo + hi;
    upk2(lo, hi, S0p); const float s0 = lo + hi;
    upk2(lo, hi, S1p); const float s1 = lo + hi;
    upk2(lo, hi, S2p); const float s2 = lo + hi;
    upk2(lo, hi, S3p); const float s3 = lo + hi;
    upk2(lo, hi, S4p); const float s4 = lo + hi;

    const float E = s0 + s2 + s4;
    const float O = s1 + s3;
    const float T = (pA ? 3.0f * S - E : E) + (pB ? 2.0f * S - O : O);
    float acc = (1.0f - 0.2f * (float)Llow) * S - 0.2f * T;

#pragma unroll
    for (int o = 16; o; o >>= 1) acc += __shfl_xor_sync(FULLM, acc, o);
    if (lane == 0) out[warp] = acc * Fsq;
}

extern "C" void kernel_launch(void* const* d_in, const int* in_sizes, int n_in,
                              void* d_out, int out_size)
{
    const float* x  = nullptr;
    const float* W  = nullptr;
    const float* b  = nullptr;
    const float* th = nullptr;
    for (int i = 0; i < n_in; ++i) {
        int sz = in_sizes[i];
        if      (sz == 4096 * 256) x  = (const float*)d_in[i];
        else if (sz == 256 * 10)   W  = (const float*)d_in[i];
        else if (sz == 10)         b  = (const float*)d_in[i];
        else if (sz == 2 * 10 * 2) th = (const float*)d_in[i];
    }
    if (!x)  x  = (const float*)d_in[0];
    if (!W)  W  = (const float*)d_in[1];
    if (!b)  b  = (const float*)d_in[2];
    if (!th) th = (const float*)d_in[3];

    int batch = out_size;
    int blocks = (batch + WPB - 1) / WPB;
    vqc_kernel<<<blocks, WPB * 32>>>(x, W, b, th, (float*)d_out, batch);
}

// round 12
// speedup vs baseline: 2.0478x; 2.0478x over previous
#include <cuda_runtime.h>

#define FULLM 0xffffffffu

typedef unsigned long long ull;

constexpr int NQ  = 10;
constexpr int DIN = 256;
constexpr int WPB = 4;      // warps (samples) per block

// ---- packed f32x2 helpers (dense encoder only) ------------------------------
__device__ __forceinline__ ull pk2(float lo, float hi) {
    ull r; asm("mov.b64 %0, {%1, %2};" : "=l"(r) : "f"(lo), "f"(hi)); return r;
}
__device__ __forceinline__ void upk2(float& lo, float& hi, ull v) {
    asm("mov.b64 {%0, %1}, %2;" : "=f"(lo), "=f"(hi) : "l"(v));
}
__device__ __forceinline__ ull fma2(ull a, ull b, ull c) {
    ull d; asm("fma.rn.f32x2 %0, %1, %2, %3;" : "=l"(d) : "l"(a), "l"(b), "l"(c)); return d;
}
__device__ __forceinline__ ull mul2(ull a, ull b) {
    ull d; asm("mul.rn.f32x2 %0, %1, %2;" : "=l"(d) : "l"(a), "l"(b)); return d;
}
__device__ __forceinline__ ull add2(ull a, ull b) {
    ull d; asm("add.rn.f32x2 %0, %1, %2;" : "=l"(d) : "l"(a), "l"(b)); return d;
}

// Heisenberg-picture closed form:
//   E_t = <phi| C1' RY2' RZ2' C2' Z_t C2 RZ2 RY2 C1 |phi>
// with |phi> = prod_q (RZ(z1_q) RY(psi_q) |0>),  psi_q = x.W+b + t0_q.
// C2' Z_t C2 = Z_0..Z_t ; RZ2 commutes ; RY2': Z_i -> c_i Z_i - s_i X_i ;
// C1': Z_i -> Z_0..Z_i , X_i -> X_i X_{i+1}.
// Product-state factorization collapses to the 4-real-state recursion below.
// Per-qubit single expectations: Z_q = cos psi, X_q = sin psi cos z1,
// Y_q = sin psi sin z1.   Recursion (level q = 1..9, cc=cos th2_q, ss=sin th2_q):
//   E_{q-1} = R10 + R00 * X_q
//   R10' = cc*( R11*Z_q + rho*Y_q )
//   R11' = cc*( R10 + R00*X_q )
//   R00' = -ss*( R10*X_q + R00 )
//   rho' =  ss*R11*Y_q - ss*rho*Z_q
//   init: R10 = c0*Z_0, R11 = c0, R00 = -s0*X_0, rho = s0*Y_0
//   final: E_9 = R10 + R00.    out = 0.1 * sum_t E_t.
// (Hand-verified symbolically against the full Pauli expansion for NQ=2 and
//  spot-checked for t=2; layer-2 RZ provably drops out.)

__global__ void __launch_bounds__(WPB * 32, 7)
vqc_kernel(const float* __restrict__ x, const float* __restrict__ W,
           const float* __restrict__ b, const float* __restrict__ theta,
           float* __restrict__ out, int batch)
{
    // Wp[p][d] = packed (W[d][2p], W[d][2p+1])
    __shared__ __align__(16) ull Wp[5][DIN];
    __shared__ float bsh[NQ];        // b[q] + theta[0][q][0]  (full L1 RY fold)
    __shared__ float4 qp[NQ];        // (cos z1, sin z1, cos th2, sin th2)

    const int tid = threadIdx.x;

    {
        const ull* Wsrc = reinterpret_cast<const ull*>(W);
        for (int m = tid; m < 5 * DIN; m += blockDim.x) {
            int d = m / 5, p = m - d * 5;
            Wp[p][d] = Wsrc[m];
        }
    }
    if (tid < NQ) {
        bsh[tid] = b[tid] + theta[tid * 2 + 0];
        float z1  = theta[tid * 2 + 1];
        float th2 = theta[(NQ + tid) * 2 + 0];
        qp[tid] = make_float4(cosf(z1), sinf(z1), cosf(th2), sinf(th2));
    }
    __syncthreads();

    const int warp = blockIdx.x * WPB + (tid >> 5);
    if (warp >= batch) return;
    const int lane = tid & 31;

    // ---------------- Dense encoder (packed: 2 qubits per accumulator) ------
    // ang[q] = psi_q = x.W[:,q] + b[q] + t0_q   (full RY angle)
    float ang[NQ];
    {
        const float4* xr = reinterpret_cast<const float4*>(x + (size_t)warp * DIN);
        float4 xv0 = xr[lane];
        float4 xv1 = xr[lane + 32];
        ull xp[8];
        xp[0] = pk2(xv0.x, xv0.x); xp[1] = pk2(xv0.y, xv0.y);
        xp[2] = pk2(xv0.z, xv0.z); xp[3] = pk2(xv0.w, xv0.w);
        xp[4] = pk2(xv1.x, xv1.x); xp[5] = pk2(xv1.y, xv1.y);
        xp[6] = pk2(xv1.z, xv1.z); xp[7] = pk2(xv1.w, xv1.w);
#pragma unroll
        for (int p = 0; p < 5; ++p) {
            const ulonglong2* wr = reinterpret_cast<const ulonglong2*>(&Wp[p][0]);
            ulonglong2 wa = wr[2 * lane];
            ulonglong2 wb = wr[2 * lane + 1];
            ulonglong2 wc = wr[2 * lane + 64];
            ulonglong2 wd = wr[2 * lane + 65];
            ull acc2 = mul2(xp[0], wa.x);
            acc2 = fma2(xp[1], wa.y, acc2);
            acc2 = fma2(xp[2], wb.x, acc2);
            acc2 = fma2(xp[3], wb.y, acc2);
            acc2 = fma2(xp[4], wc.x, acc2);
            acc2 = fma2(xp[5], wc.y, acc2);
            acc2 = fma2(xp[6], wd.x, acc2);
            acc2 = fma2(xp[7], wd.y, acc2);
#pragma unroll
            for (int o = 16; o; o >>= 1)
                acc2 = add2(acc2, __shfl_xor_sync(FULLM, acc2, o));
            float a0, a1; upk2(a0, a1, acc2);
            ang[2 * p]     = a0 + bsh[2 * p];
            ang[2 * p + 1] = a1 + bsh[2 * p + 1];
        }
    }

    // ---------------- Transfer-matrix chain (all lanes redundantly) ---------
    float sn, cs;
    float4 p0 = qp[0];
    __sincosf(ang[0], &sn, &cs);
    float X = sn * p0.x, Y = sn * p0.y, Z = cs;
    float R10 = p0.z * Z;
    float R11 = p0.z;
    float R00 = -p0.w * X;
    float rho = p0.w * Y;
    float acc = 0.f;

#pragma unroll
    for (int q = 1; q < NQ; ++q) {
        float4 pq = qp[q];
        __sincosf(ang[q], &sn, &cs);
        X = sn * pq.x; Y = sn * pq.y; Z = cs;
        // E_{q-1} uses qubit-q X for the dangling X_{t+1}
        acc += R10 + R00 * X;
        const float cc = pq.z, ss = pq.w;
        float n10 = R11 * (cc * Z) + rho * (cc * Y);
        float n11 = R10 * cc + R00 * (cc * X);
        float n00 = -(R10 * (ss * X) + R00 * ss);
        float nrh = R11 * (ss * Y) - rho * (ss * Z);
        R10 = n10; R11 = n11; R00 = n00; rho = nrh;
    }
    // t = 9: no dangling X (chain ends at qubit 9)
    acc += R10 + R00;

    if (lane == 0) out[warp] = acc * 0.1f;
}

extern "C" void kernel_launch(void* const* d_in, const int* in_sizes, int n_in,
                              void* d_out, int out_size)
{
    const float* x  = nullptr;
    const float* W  = nullptr;
    const float* b  = nullptr;
    const float* th = nullptr;
    for (int i = 0; i < n_in; ++i) {
        int sz = in_sizes[i];
        if      (sz == 4096 * 256) x  = (const float*)d_in[i];
        else if (sz == 256 * 10)   W  = (const float*)d_in[i];
        else if (sz == 10)         b  = (const float*)d_in[i];
        else if (sz == 2 * 10 * 2) th = (const float*)d_in[i];
    }
    if (!x)  x  = (const float*)d_in[0];
    if (!W)  W  = (const float*)d_in[1];
    if (!b)  b  = (const float*)d_in[2];
    if (!th) th = (const float*)d_in[3];

    int batch = out_size;
    int blocks = (batch + WPB - 1) / WPB;
    vqc_kernel<<<blocks, WPB * 32>>>(x, W, b, th, (float*)d_out, batch);
}